// round 6
// baseline (speedup 1.0000x reference)
#include <cuda_runtime.h>
#include <cuda_fp16.h>
#include <math.h>
#include <stdint.h>

#define BATCH   32
#define SEQ     197
#define EMB     768
#define EMB3    2304
#define HEADS   12
#define HD      64
#define KW      197
#define NLAYERS 12
#define HIDDEN  3072
#define TOK     (BATCH*SEQ)       // 6304
#define BH      (BATCH*HEADS)     // 384
#define ROWSA   (BH*SEQ)          // 75648
#define SPAD    224               // padded stride for A rows (halfs)
#define KWPAD   208               // padded K for out kernel

#define CDIV(a,b) (((a)+(b)-1)/(b))

// ---------------- scratch ----------------
static __device__ float  g_x1 [TOK*EMB];
static __device__ float  g_x2 [TOK*EMB];
static __device__ __half g_xn [TOK*EMB];
static __device__ __half g_qkv[TOK*EMB3];
static __device__ __half g_A  [(size_t)BH*SEQ*SPAD];
static __device__ __half g_y  [BH*KW*HD];
static __device__ __half g_h  [TOK*HIDDEN];
// half weights, pre-transposed to [N][K]
static __device__ __half g_wqkv [EMB3*EMB];
static __device__ __half g_wfc  [256*SPAD];   // [kw][m] padded
static __device__ __half g_w1   [HIDDEN*EMB];
static __device__ __half g_w2   [EMB*HIDDEN];
static __device__ __half g_wfc2t[256*KWPAD];

// ---------------- helpers ----------------
__device__ __forceinline__ void cpasync16(uint32_t dst, const void* src, int srcbytes) {
    asm volatile("cp.async.cg.shared.global [%0], [%1], 16, %2;\n"
                 :: "r"(dst), "l"(src), "r"(srcbytes));
}
__device__ __forceinline__ void cp_commit() { asm volatile("cp.async.commit_group;\n"); }
__device__ __forceinline__ void cp_wait0() { asm volatile("cp.async.wait_group 0;\n"); }
__device__ __forceinline__ void cp_wait1() { asm volatile("cp.async.wait_group 1;\n"); }

#define MMA_F16(acc, afr, bfr)                                               \
    asm volatile(                                                            \
        "mma.sync.aligned.m16n8k16.row.col.f32.f16.f16.f32 "                 \
        "{%0,%1,%2,%3}, {%4,%5,%6,%7}, {%8,%9}, {%0,%1,%2,%3};\n"            \
        : "+f"((acc)[0]), "+f"((acc)[1]), "+f"((acc)[2]), "+f"((acc)[3])     \
        : "r"((afr)[0]), "r"((afr)[1]), "r"((afr)[2]), "r"((afr)[3]),        \
          "r"((bfr)[0]), "r"((bfr)[1]))

#define LDSM_X4_T(r0, r1, r2, r3, addr)                                      \
    asm volatile("ldmatrix.sync.aligned.m8n8.x4.trans.shared.b16 "           \
                 "{%0,%1,%2,%3}, [%4];"                                      \
                 : "=r"(r0), "=r"(r1), "=r"(r2), "=r"(r3) : "r"(addr))

__device__ __forceinline__ uint32_t h2u(__half2 h) {
    uint32_t u; *((__half2*)&u) = h; return u;
}

// ---------------- elementwise ----------------
__global__ void init_copy(const float* __restrict__ x, float* __restrict__ x1,
                          float* __restrict__ x2, int n) {
    int i = blockIdx.x * blockDim.x + threadIdx.x;
    if (i < n) { float v = x[i]; x1[i] = v; x2[i] = v; }
}

__global__ void finalize_k(const float* __restrict__ x1, const float* __restrict__ x2,
                           float* __restrict__ out, int n) {
    int i = blockIdx.x * blockDim.x + threadIdx.x;
    if (i < n) out[i] = 0.5f * (x1[i] + x2[i]);
}

// transpose [K][N] float -> [N][K] half
__global__ void prep_wT(const float* __restrict__ s, __half* __restrict__ d,
                        int K, int N) {
    int i = blockIdx.x * blockDim.x + threadIdx.x;
    if (i < N * K) {
        int n = i / K, k = i % K;
        d[i] = __float2half_rn(s[(size_t)k * N + n]);
    }
}

// fc_w (SEQ,KW) -> Bt[256][SPAD]: Bt[n=kw][k=m]
__global__ void prep_fcT(const float* __restrict__ s, __half* __restrict__ d) {
    int i = blockIdx.x * blockDim.x + threadIdx.x;
    if (i < 256 * SPAD) {
        int n = i / SPAD, k = i % SPAD;
        d[i] = (n < KW && k < SEQ) ? __float2half_rn(s[k * KW + n]) : __float2half(0.f);
    }
}

// fc2_w (KW,SEQ) -> Wt[256][KWPAD]: Wt[n2][k=kw]
__global__ void prep_fc2T(const float* __restrict__ s, __half* __restrict__ d) {
    int i = blockIdx.x * blockDim.x + threadIdx.x;
    if (i < 256 * KWPAD) {
        int n2 = i / KWPAD, k = i % KWPAD;
        d[i] = (n2 < SEQ && k < KW) ? __float2half_rn(s[k * SEQ + n2]) : __float2half(0.f);
    }
}

// ---------------- layernorm rows of 768 -> half ----------------
__global__ void ln_row768(const float* __restrict__ x, const float* __restrict__ g,
                          const float* __restrict__ b, __half* __restrict__ out) {
    int row = blockIdx.x;
    const float* xr = x + (size_t)row * EMB;
    __half* orow = out + (size_t)row * EMB;
    int tid = threadIdx.x;  // 256
    float s = 0.f, ss = 0.f;
    for (int i = tid; i < EMB; i += 256) { float v = xr[i]; s += v; ss += v * v; }
    __shared__ float rs[8], rss[8];
    #pragma unroll
    for (int o = 16; o; o >>= 1) {
        s  += __shfl_xor_sync(0xffffffffu, s,  o);
        ss += __shfl_xor_sync(0xffffffffu, ss, o);
    }
    if ((tid & 31) == 0) { rs[tid >> 5] = s; rss[tid >> 5] = ss; }
    __syncthreads();
    if (tid < 32) {
        float a = (tid < 8) ? rs[tid]  : 0.f;
        float c = (tid < 8) ? rss[tid] : 0.f;
        #pragma unroll
        for (int o = 4; o; o >>= 1) {
            a += __shfl_xor_sync(0xffffffffu, a, o);
            c += __shfl_xor_sync(0xffffffffu, c, o);
        }
        if (tid == 0) { rs[0] = a; rss[0] = c; }
    }
    __syncthreads();
    float mu  = rs[0] * (1.0f / EMB);
    float var = rss[0] * (1.0f / EMB) - mu * mu;
    float inv = rsqrtf(var + 1e-5f);
    for (int i = tid; i < EMB; i += 256)
        orow[i] = __float2half_rn((xr[i] - mu) * inv * g[i] + b[i]);
}

// ================= fp16 GEMM: C = A[M,K] @ Bt[N,K]^T ======================
#define GST 40
#define GSTG (128*GST)

template <int EPI>
__global__ void __launch_bounds__(256) gemm_f16(
    const __half* __restrict__ A, const __half* __restrict__ B,
    const float* __restrict__ bias, const float* __restrict__ res,
    __half* __restrict__ Ch, float* __restrict__ Cf,
    int ldc, int M, int N, int K)
{
    __shared__ __half As[2 * GSTG];
    __shared__ __half Bs[2 * GSTG];
    const int tid  = threadIdx.x;
    const int warp = tid >> 5, lane = tid & 31;
    const int wm = warp >> 2, wn = warp & 3;
    const int g = lane >> 2, t = lane & 3;
    const int m0 = blockIdx.y * 128, n0 = blockIdx.x * 128;

    const uint32_t as_u = (uint32_t)__cvta_generic_to_shared(As);
    const uint32_t bs_u = (uint32_t)__cvta_generic_to_shared(Bs);

    const int r0i = tid >> 2, seg = (tid & 3) * 8;
    const int r1i = (tid + 256) >> 2;

    float acc[4][4][4];
    #pragma unroll
    for (int i = 0; i < 4; i++)
        #pragma unroll
        for (int j = 0; j < 4; j++)
            #pragma unroll
            for (int r = 0; r < 4; r++) acc[i][j][r] = 0.f;

    const int nch = K / 32;
    {
        cpasync16(as_u + (size_t)(r0i * GST + seg) * 2,
                  A + (size_t)(m0 + r0i) * K + seg, (m0 + r0i < M) ? 16 : 0);
        cpasync16(as_u + (size_t)(r1i * GST + seg) * 2,
                  A + (size_t)(m0 + r1i) * K + seg, (m0 + r1i < M) ? 16 : 0);
        cpasync16(bs_u + (size_t)(r0i * GST + seg) * 2,
                  B + (size_t)(n0 + r0i) * K + seg, 16);
        cpasync16(bs_u + (size_t)(r1i * GST + seg) * 2,
                  B + (size_t)(n0 + r1i) * K + seg, 16);
        cp_commit();
    }

    for (int c = 0; c < nch; ++c) {
        if (c + 1 < nch) {
            const int k0 = (c + 1) * 32;
            const int so = ((c + 1) & 1) * GSTG;
            cpasync16(as_u + (size_t)(so + r0i * GST + seg) * 2,
                      A + (size_t)(m0 + r0i) * K + k0 + seg, (m0 + r0i < M) ? 16 : 0);
            cpasync16(as_u + (size_t)(so + r1i * GST + seg) * 2,
                      A + (size_t)(m0 + r1i) * K + k0 + seg, (m0 + r1i < M) ? 16 : 0);
            cpasync16(bs_u + (size_t)(so + r0i * GST + seg) * 2,
                      B + (size_t)(n0 + r0i) * K + k0 + seg, 16);
            cpasync16(bs_u + (size_t)(so + r1i * GST + seg) * 2,
                      B + (size_t)(n0 + r1i) * K + k0 + seg, 16);
            cp_commit();
            cp_wait1();
        } else {
            cp_wait0();
        }
        __syncthreads();

        const uint32_t* as32 = (const uint32_t*)(As + (c & 1) * GSTG);
        const uint32_t* bs32 = (const uint32_t*)(Bs + (c & 1) * GSTG);

        #pragma unroll
        for (int kk = 0; kk < 2; ++kk) {
            const int kb2 = kk * 8;
            uint32_t afr[4][4], bfr[4][2];
            #pragma unroll
            for (int mi = 0; mi < 4; mi++) {
                int m = wm * 64 + mi * 16 + g;
                afr[mi][0] = as32[(m    ) * 20 + kb2 + t];
                afr[mi][1] = as32[(m + 8) * 20 + kb2 + t];
                afr[mi][2] = as32[(m    ) * 20 + kb2 + t + 4];
                afr[mi][3] = as32[(m + 8) * 20 + kb2 + t + 4];
            }
            #pragma unroll
            for (int nj = 0; nj < 4; nj++) {
                int n = wn * 32 + nj * 8 + g;
                bfr[nj][0] = bs32[n * 20 + kb2 + t];
                bfr[nj][1] = bs32[n * 20 + kb2 + t + 4];
            }
            #pragma unroll
            for (int mi = 0; mi < 4; mi++)
                #pragma unroll
                for (int nj = 0; nj < 4; nj++)
                    MMA_F16(acc[mi][nj], afr[mi], bfr[nj]);
        }
        __syncthreads();
    }

    #pragma unroll
    for (int mi = 0; mi < 4; mi++) {
        int r0 = m0 + wm * 64 + mi * 16 + g;
        #pragma unroll
        for (int nj = 0; nj < 4; nj++) {
            int cb = n0 + wn * 32 + nj * 8 + 2 * t;
            #pragma unroll
            for (int half_ = 0; half_ < 2; half_++) {
                int gm = r0 + half_ * 8;
                if (gm >= M) continue;
                #pragma unroll
                for (int q = 0; q < 2; q++) {
                    int gn = cb + q;
                    if (gn >= N) continue;
                    float v = acc[mi][nj][half_ * 2 + q];
                    if (EPI == 1 || EPI == 2 || EPI == 3) v += bias[gn];
                    if (EPI == 2)
                        v = 0.5f * v * (1.0f + erff(v * 0.70710678118654752f));
                    if (EPI == 3)
                        Cf[(size_t)gm * ldc + gn] = v + res[(size_t)gm * ldc + gn];
                    else
                        Ch[(size_t)gm * ldc + gn] = __float2half_rn(v);
                }
            }
        }
    }
}

// ============ FUSED attention front: QK^T -> @fc_w -> LN -> softmax =========
// One block per (128 q-rows, z). Tile: 128 rows x 224 kw cols, loop over
// key chunks of 32. S stays in registers (C-frag -> A-frag reuse).
// Warps: 8 = 4(m: 32 rows) x 2(n: 112 cols). Writes probs (half) to A.
#define AF_SMEM (68224)

__global__ void __launch_bounds__(256) attn_front(
    const __half* __restrict__ qkv, const __half* __restrict__ Wfc,
    const float* __restrict__ fc_b,
    const float* __restrict__ ln_g, const float* __restrict__ ln_b,
    __half* __restrict__ Aout)
{
    extern __shared__ char smraw[];
    __half* Qs = (__half*)smraw;                 // 128*72
    __half* Kc = Qs + 128 * 72;                  // 2 * 32*72
    __half* Wc = Kc + 2 * 32 * 72;               // 2 * 224*40
    float* red_s  = (float*)(Wc + 2 * 224 * 40); // 256
    float* red_ss = red_s + 256;                 // 256
    float* biasf  = red_ss + 256;                // 224
    float* lngs   = biasf + 224;                 // 224
    float* lnbs   = lngs + 224;                  // 224

    const int z = blockIdx.y, b = z / HEADS, h = z % HEADS;
    const int m0q = blockIdx.x * 128;
    const __half* qb = qkv + (size_t)b * SEQ * EMB3 + h * HD;
    const __half* kb = qb + EMB;

    const int tid = threadIdx.x;
    const int warp = tid >> 5, lane = tid & 31;
    const int wm = warp >> 1, wn = warp & 1;
    const int g = lane >> 2, t = lane & 3;

    const uint32_t qs_u = (uint32_t)__cvta_generic_to_shared(Qs);
    const uint32_t kc_u = (uint32_t)__cvta_generic_to_shared(Kc);
    const uint32_t wc_u = (uint32_t)__cvta_generic_to_shared(Wc);

    // biases -> smem
    for (int i = tid; i < 224; i += 256) {
        biasf[i] = (i < KW) ? fc_b[i] : 0.f;
        lngs[i]  = (i < KW) ? ln_g[i] : 0.f;
        lnbs[i]  = (i < KW) ? ln_b[i] : 0.f;
    }

    // group 0: Q tile (128 x 64 halfs)
    #pragma unroll
    for (int i = 0; i < 4; i++) {
        int flat = tid + i * 256;
        int r = flat >> 3, sg = (flat & 7) * 8;
        cpasync16(qs_u + (uint32_t)(r * 72 + sg) * 2,
                  qb + (size_t)(m0q + r) * EMB3 + sg, (m0q + r < SEQ) ? 16 : 0);
    }
    cp_commit();
    // group 1: chunk 0 (Kc stage0, Wc stage0)
    {
        int r = tid >> 3, sg = (tid & 7) * 8;
        cpasync16(kc_u + (uint32_t)(r * 72 + sg) * 2,
                  kb + (size_t)r * EMB3 + sg, (r < SEQ) ? 16 : 0);
        #pragma unroll
        for (int i = 0; i < 4; i++) {
            int flat = tid + i * 256;
            if (flat < 896) {
                int rr = flat >> 2, s2 = (flat & 3) * 8;
                cpasync16(wc_u + (uint32_t)(rr * 40 + s2) * 2,
                          Wfc + (size_t)rr * SPAD + s2, 16);
            }
        }
        cp_commit();
    }
    cp_wait1();           // Q complete
    __syncthreads();

    // hoist Q fragments
    const uint32_t* qs32 = (const uint32_t*)Qs;
    uint32_t qfr[2][4][4];
    #pragma unroll
    for (int mi = 0; mi < 2; mi++) {
        int m = wm * 32 + mi * 16 + g;
        #pragma unroll
        for (int s = 0; s < 4; s++) {
            qfr[mi][s][0] = qs32[(m    ) * 36 + s * 8 + t];
            qfr[mi][s][1] = qs32[(m + 8) * 36 + s * 8 + t];
            qfr[mi][s][2] = qs32[(m    ) * 36 + s * 8 + t + 4];
            qfr[mi][s][3] = qs32[(m + 8) * 36 + s * 8 + t + 4];
        }
    }

    float acc[2][14][4];
    #pragma unroll
    for (int i = 0; i < 2; i++)
        #pragma unroll
        for (int j = 0; j < 14; j++)
            #pragma unroll
            for (int r = 0; r < 4; r++) acc[i][j][r] = 0.f;

    for (int c = 0; c < 7; ++c) {
        if (c < 6) {
            const int k0 = (c + 1) * 32;
            const int st = (c + 1) & 1;
            int r = tid >> 3, sg = (tid & 7) * 8;
            cpasync16(kc_u + (uint32_t)(st * 32 * 72 + r * 72 + sg) * 2,
                      kb + (size_t)(k0 + r) * EMB3 + sg, (k0 + r < SEQ) ? 16 : 0);
            #pragma unroll
            for (int i = 0; i < 4; i++) {
                int flat = tid + i * 256;
                if (flat < 896) {
                    int rr = flat >> 2, s2 = (flat & 3) * 8;
                    cpasync16(wc_u + (uint32_t)(st * 224 * 40 + rr * 40 + s2) * 2,
                              Wfc + (size_t)rr * SPAD + k0 + s2, 16);
                }
            }
            cp_commit();
            cp_wait1();
        } else {
            cp_wait0();
        }
        __syncthreads();

        const int st = c & 1;
        const uint32_t* kc32 = (const uint32_t*)(Kc + st * 32 * 72);
        const uint32_t* wc32 = (const uint32_t*)(Wc + st * 224 * 40);

        // ---- first mma: S chunk [32 rows][32 keys]
        float sacc[2][4][4];
        #pragma unroll
        for (int i = 0; i < 2; i++)
            #pragma unroll
            for (int j = 0; j < 4; j++)
                #pragma unroll
                for (int r = 0; r < 4; r++) sacc[i][j][r] = 0.f;

        #pragma unroll
        for (int s = 0; s < 4; s++) {
            uint32_t kfr[4][2];
            #pragma unroll
            for (int njq = 0; njq < 4; njq++) {
                int n = njq * 8 + g;
                kfr[njq][0] = kc32[n * 36 + s * 8 + t];
                kfr[njq][1] = kc32[n * 36 + s * 8 + t + 4];
            }
            #pragma unroll
            for (int mi = 0; mi < 2; mi++)
                #pragma unroll
                for (int njq = 0; njq < 4; njq++)
                    MMA_F16(sacc[mi][njq], qfr[mi][s], kfr[njq]);
        }

        // ---- convert S C-frags -> A-frags (scale 1/8, fp16)
        uint32_t safr[2][2][4];
        #pragma unroll
        for (int mi = 0; mi < 2; mi++)
            #pragma unroll
            for (int s2 = 0; s2 < 2; s2++) {
                safr[mi][s2][0] = h2u(__floats2half2_rn(sacc[mi][2*s2][0] * 0.125f,
                                                        sacc[mi][2*s2][1] * 0.125f));
                safr[mi][s2][1] = h2u(__floats2half2_rn(sacc[mi][2*s2][2] * 0.125f,
                                                        sacc[mi][2*s2][3] * 0.125f));
                safr[mi][s2][2] = h2u(__floats2half2_rn(sacc[mi][2*s2+1][0] * 0.125f,
                                                        sacc[mi][2*s2+1][1] * 0.125f));
                safr[mi][s2][3] = h2u(__floats2half2_rn(sacc[mi][2*s2+1][2] * 0.125f,
                                                        sacc[mi][2*s2+1][3] * 0.125f));
            }

        // ---- second mma: acc += S_chunk @ fc_w_chunk
        #pragma unroll
        for (int s2 = 0; s2 < 2; s2++)
            #pragma unroll
            for (int nj = 0; nj < 14; nj++) {
                int n = wn * 112 + nj * 8 + g;
                uint32_t wfr[2];
                wfr[0] = wc32[n * 20 + s2 * 8 + t];
                wfr[1] = wc32[n * 20 + s2 * 8 + t + 4];
                #pragma unroll
                for (int mi = 0; mi < 2; mi++)
                    MMA_F16(acc[mi][nj], safr[mi][s2], wfr);
            }
        __syncthreads();
    }

    // ================= epilogue: +bias, LN(row), softmax(row) ===============
    // phase 1: sum & sumsq
    float mu_[2][2], inv_[2][2];
    #pragma unroll
    for (int mi = 0; mi < 2; mi++)
        #pragma unroll
        for (int hf = 0; hf < 2; hf++) {
            float s = 0.f, ss = 0.f;
            #pragma unroll
            for (int nj = 0; nj < 14; nj++)
                #pragma unroll
                for (int q = 0; q < 2; q++) {
                    int gn = wn * 112 + nj * 8 + 2 * t + q;
                    if (gn < KW) {
                        float v = acc[mi][nj][hf * 2 + q] + biasf[gn];
                        acc[mi][nj][hf * 2 + q] = v;
                        s += v; ss += v * v;
                    }
                }
            s  += __shfl_xor_sync(0xffffffffu, s, 1);
            s  += __shfl_xor_sync(0xffffffffu, s, 2);
            ss += __shfl_xor_sync(0xffffffffu, ss, 1);
            ss += __shfl_xor_sync(0xffffffffu, ss, 2);
            if (t == 0) {
                int row = wm * 32 + mi * 16 + g + 8 * hf;
                red_s [row * 2 + wn] = s;
                red_ss[row * 2 + wn] = ss;
            }
        }
    __syncthreads();
    #pragma unroll
    for (int mi = 0; mi < 2; mi++)
        #pragma unroll
        for (int hf = 0; hf < 2; hf++) {
            int row = wm * 32 + mi * 16 + g + 8 * hf;
            float s  = red_s [row * 2] + red_s [row * 2 + 1];
            float ss = red_ss[row * 2] + red_ss[row * 2 + 1];
            float mu = s * (1.0f / KW);
            float var = ss * (1.0f / KW) - mu * mu;
            mu_[mi][hf] = mu;
            inv_[mi][hf] = rsqrtf(var + 1e-5f);
        }
    __syncthreads();
    // phase 2: LN transform + row max
    float mx_[2][2];
    #pragma unroll
    for (int mi = 0; mi < 2; mi++)
        #pragma unroll
        for (int hf = 0; hf < 2; hf++) {
            float mx = -1e30f;
            #pragma unroll
            for (int nj = 0; nj < 14; nj++)
                #pragma unroll
                for (int q = 0; q < 2; q++) {
                    int gn = wn * 112 + nj * 8 + 2 * t + q;
                    if (gn < KW) {
                        float zv = (acc[mi][nj][hf * 2 + q] - mu_[mi][hf]) * inv_[mi][hf]
                                   * lngs[gn] + lnbs[gn];
                        acc[mi][nj][hf * 2 + q] = zv;
                        mx = fmaxf(mx, zv);
                    }
                }
            mx = fmaxf(mx, __shfl_xor_sync(0xffffffffu, mx, 1));
            mx = fmaxf(mx, __shfl_xor_sync(0xffffffffu, mx, 2));
            if (t == 0) {
                int row = wm * 32 + mi * 16 + g + 8 * hf;
                red_s[row * 2 + wn] = mx;
            }
        }
    __syncthreads();
    #pragma unroll
    for (int mi = 0; mi < 2; mi++)
        #pragma unroll
        for (int hf = 0; hf < 2; hf++) {
            int row = wm * 32 + mi * 16 + g + 8 * hf;
            mx_[mi][hf] = fmaxf(red_s[row * 2], red_s[row * 2 + 1]);
        }
    __syncthreads();
    // phase 3: exp + row sum
    float rinv_[2][2];
    #pragma unroll
    for (int mi = 0; mi < 2; mi++)
        #pragma unroll
        for (int hf = 0; hf < 2; hf++) {
            float s = 0.f;
            #pragma unroll
            for (int nj = 0; nj < 14; nj++)
                #pragma unroll
                for (int q = 0; q < 2; q++) {
                    int gn = wn * 112 + nj * 8 + 2 * t + q;
                    if (gn < KW) {
                        float e = __expf(acc[mi][nj][hf * 2 + q] - mx_[mi][hf]);
                        acc[mi][nj][hf * 2 + q] = e;
                        s += e;
                    }
                }
            s += __shfl_xor_sync(0xffffffffu, s, 1);
            s += __shfl_xor_sync(0xffffffffu, s, 2);
            if (t == 0) {
                int row = wm * 32 + mi * 16 + g + 8 * hf;
                red_s[row * 2 + wn] = s;
            }
        }
    __syncthreads();
    #pragma unroll
    for (int mi = 0; mi < 2; mi++)
        #pragma unroll
        for (int hf = 0; hf < 2; hf++) {
            int row = wm * 32 + mi * 16 + g + 8 * hf;
            rinv_[mi][hf] = 1.0f / (red_s[row * 2] + red_s[row * 2 + 1]);
        }
    // phase 4: write probs (half), zero pad cols
    __half* Az = Aout + (size_t)z * SEQ * SPAD;
    #pragma unroll
    for (int mi = 0; mi < 2; mi++)
        #pragma unroll
        for (int hf = 0; hf < 2; hf++) {
            int gm = m0q + wm * 32 + mi * 16 + g + 8 * hf;
            if (gm >= SEQ) continue;
            #pragma unroll
            for (int nj = 0; nj < 14; nj++) {
                int gn0 = wn * 112 + nj * 8 + 2 * t;
                float p0 = (gn0     < KW) ? acc[mi][nj][hf * 2    ] * rinv_[mi][hf] : 0.f;
                float p1 = (gn0 + 1 < KW) ? acc[mi][nj][hf * 2 + 1] * rinv_[mi][hf] : 0.f;
                *(__half2*)(Az + (size_t)gm * SPAD + gn0) = __floats2half2_rn(p0, p1);
            }
        }
}

// ---------------- P^T V fp16: y[z,kw,d] = sum_n P[n,kw] V[n,d] -------------
__global__ void __launch_bounds__(256) pv_f16(const __half* __restrict__ A,
                                              const __half* __restrict__ qkv,
                                              __half* __restrict__ y)
{
    __shared__ __half Ps[16 * 136];
    __shared__ __half Vs[16 * 72];
    const int z = blockIdx.y, b = z / HEADS, h = z % HEADS;
    const __half* Ab = A + (size_t)z * SEQ * SPAD;
    const __half* Vb = qkv + (size_t)b * SEQ * EMB3 + h * HD + 2 * EMB;
    const int m0 = blockIdx.x * 128;
    const int tid = threadIdx.x;
    const int warp = tid >> 5, lane = tid & 31;
    const int wm = warp >> 1, wn = warp & 1;
    const int g = lane >> 2, t = lane & 3;
    const uint32_t ps_u = (uint32_t)__cvta_generic_to_shared(Ps);
    const uint32_t vs_u = (uint32_t)__cvta_generic_to_shared(Vs);

    const int arow = (lane & 7) + ((lane >> 4) << 3);
    const int acol8 = ((lane >> 3) & 1) << 3;
    const int brow = (lane & 7) + (((lane >> 3) & 1) << 3);
    const int bcol8 = (lane >> 4) << 3;

    float acc[2][4][4];
    #pragma unroll
    for (int i = 0; i < 2; i++)
        #pragma unroll
        for (int j = 0; j < 4; j++)
            #pragma unroll
            for (int r = 0; r < 4; r++) acc[i][j][r] = 0.f;

    for (int c = 0; c < KWPAD / 16; ++c) {
        const int k0 = c * 16;
        {
            int r = tid >> 4, sg = (tid & 15) * 8;
            cpasync16(ps_u + (size_t)(r * 136 + sg) * 2,
                      Ab + (size_t)(k0 + r) * SPAD + m0 + sg,
                      (k0 + r < SEQ && m0 + sg < SPAD) ? 16 : 0);
        }
        if (tid < 128) {
            int r = tid >> 3, sg = (tid & 7) * 8;
            cpasync16(vs_u + (size_t)(r * 72 + sg) * 2,
                      Vb + (size_t)(k0 + r) * EMB3 + sg, (k0 + r < SEQ) ? 16 : 0);
        }
        cp_commit(); cp_wait0();
        __syncthreads();

        uint32_t afr[2][4], bfr[4][2];
        #pragma unroll
        for (int mi = 0; mi < 2; mi++) {
            uint32_t addr = ps_u + (size_t)(arow * 136 + wm * 32 + mi * 16 + acol8) * 2;
            LDSM_X4_T(afr[mi][0], afr[mi][1], afr[mi][2], afr[mi][3], addr);
        }
        #pragma unroll
        for (int njp = 0; njp < 2; njp++) {
            uint32_t addr = vs_u + (size_t)(brow * 72 + wn * 32 + njp * 16 + bcol8) * 2;
            LDSM_X4_T(bfr[njp * 2][0], bfr[njp * 2][1],
                      bfr[njp * 2 + 1][0], bfr[njp * 2 + 1][1], addr);
        }
        #pragma unroll
        for (int mi = 0; mi < 2; mi++)
            #pragma unroll
            for (int nj = 0; nj < 4; nj++)
                MMA_F16(acc[mi][nj], afr[mi], bfr[nj]);
        __syncthreads();
    }

    __half* yz = y + (size_t)z * KW * HD;
    #pragma unroll
    for (int mi = 0; mi < 2; mi++) {
        int r0 = m0 + wm * 32 + mi * 16 + g;
        #pragma unroll
        for (int nj = 0; nj < 4; nj++) {
            int cb = wn * 32 + nj * 8 + 2 * t;
            #pragma unroll
            for (int half_ = 0; half_ < 2; half_++) {
                int gm = r0 + half_ * 8;
                if (gm >= KW) continue;
                #pragma unroll
                for (int q = 0; q < 2; q++)
                    yz[(size_t)gm * HD + cb + q] =
                        __float2half_rn(acc[mi][nj][half_ * 2 + q]);
            }
        }
    }
}

// --------- fc2: x1[b,n2,h,d] += sum_k Wt[n2,k] y[z,k,d] + fc2_b[n2] --------
__global__ void __launch_bounds__(256) out_f16(const __half* __restrict__ Wt,
                                               const __half* __restrict__ y,
                                               const float* __restrict__ bias,
                                               float* __restrict__ x1)
{
    __shared__ __half As[128 * 24];
    __shared__ __half Ys[16 * 72];
    const int z = blockIdx.y, b = z / HEADS, h = z % HEADS;
    const __half* yb = y + (size_t)z * KW * HD;
    const int m0 = blockIdx.x * 128;
    const int tid = threadIdx.x;
    const int warp = tid >> 5, lane = tid & 31;
    const int wm = warp >> 1, wn = warp & 1;
    const int g = lane >> 2, t = lane & 3;
    const uint32_t as_u = (uint32_t)__cvta_generic_to_shared(As);
    const uint32_t ys_u = (uint32_t)__cvta_generic_to_shared(Ys);

    const int brow = (lane & 7) + (((lane >> 3) & 1) << 3);
    const int bcol8 = (lane >> 4) << 3;

    float acc[2][4][4];
    #pragma unroll
    for (int i = 0; i < 2; i++)
        #pragma unroll
        for (int j = 0; j < 4; j++)
            #pragma unroll
            for (int r = 0; r < 4; r++) acc[i][j][r] = 0.f;

    for (int c = 0; c < KWPAD / 16; ++c) {
        const int k0 = c * 16;
        {
            int r = tid >> 1, sg = (tid & 1) * 8;
            cpasync16(as_u + (size_t)(r * 24 + sg) * 2,
                      Wt + (size_t)(m0 + r) * KWPAD + k0 + sg, 16);
        }
        if (tid < 128) {
            int r = tid >> 3, sg = (tid & 7) * 8;
            cpasync16(ys_u + (size_t)(r * 72 + sg) * 2,
                      yb + (size_t)(k0 + r) * HD + sg, (k0 + r < KW) ? 16 : 0);
        }
        cp_commit(); cp_wait0();
        __syncthreads();

        const uint32_t* as32 = (const uint32_t*)As;
        uint32_t afr[2][4], bfr[4][2];
        #pragma unroll
        for (int mi = 0; mi < 2; mi++) {
            int m = wm * 32 + mi * 16 + g;
            afr[mi][0] = as32[(m    ) * 12 + t];
            afr[mi][1] = as32[(m + 8) * 12 + t];
            afr[mi][2] = as32[(m    ) * 12 + t + 4];
            afr[mi][3] = as32[(m + 8) * 12 + t + 4];
        }
        #pragma unroll
        for (int njp = 0; njp < 2; njp++) {
            uint32_t addr = ys_u + (size_t)(brow * 72 + wn * 32 + njp * 16 + bcol8) * 2;
            LDSM_X4_T(bfr[njp * 2][0], bfr[njp * 2][1],
                      bfr[njp * 2 + 1][0], bfr[njp * 2 + 1][1], addr);
        }
        #pragma unroll
        for (int mi = 0; mi < 2; mi++)
            #pragma unroll
            for (int nj = 0; nj < 4; nj++)
                MMA_F16(acc[mi][nj], afr[mi], bfr[nj]);
        __syncthreads();
    }

    #pragma unroll
    for (int mi = 0; mi < 2; mi++) {
        int r0 = m0 + wm * 32 + mi * 16 + g;
        #pragma unroll
        for (int nj = 0; nj < 4; nj++) {
            int cb = wn * 32 + nj * 8 + 2 * t;
            #pragma unroll
            for (int half_ = 0; half_ < 2; half_++) {
                int gm = r0 + half_ * 8;
                if (gm >= SEQ) continue;
                float bv = bias[gm];
                #pragma unroll
                for (int q = 0; q < 2; q++) {
                    size_t idx = ((size_t)(b * SEQ + gm)) * EMB + h * HD + cb + q;
                    x1[idx] += acc[mi][nj][half_ * 2 + q] + bv;
                }
            }
        }
    }
}

// ---------------- launch ----------------
extern "C" void kernel_launch(void* const* d_in, const int* in_sizes, int n_in,
                              void* d_out, int out_size) {
    (void)in_sizes; (void)n_in; (void)out_size;
    const float* x         = (const float*)d_in[0];
    const float* qkv_w     = (const float*)d_in[1];
    const float* fc_w      = (const float*)d_in[2];
    const float* fc_b      = (const float*)d_in[3];
    const float* attn_ln_g = (const float*)d_in[4];
    const float* attn_ln_b = (const float*)d_in[5];
    const float* fc2_w     = (const float*)d_in[6];
    const float* fc2_b     = (const float*)d_in[7];
    const float* mlp_w1    = (const float*)d_in[8];
    const float* mlp_b1    = (const float*)d_in[9];
    const float* mlp_w2    = (const float*)d_in[10];
    const float* mlp_b2    = (const float*)d_in[11];
    const float* f_ln_g    = (const float*)d_in[12];
    const float* f_ln_b    = (const float*)d_in[13];
    const float* gl_ln_g   = (const float*)d_in[14];
    const float* gl_ln_b   = (const float*)d_in[15];

    float *px1, *px2;
    __half *pxn, *pqkv, *pA, *py, *ph;
    __half *pwqkv, *pwfc, *pw1, *pw2, *pwfc2t;
    cudaGetSymbolAddress((void**)&px1,  g_x1);
    cudaGetSymbolAddress((void**)&px2,  g_x2);
    cudaGetSymbolAddress((void**)&pxn,  g_xn);
    cudaGetSymbolAddress((void**)&pqkv, g_qkv);
    cudaGetSymbolAddress((void**)&pA,   g_A);
    cudaGetSymbolAddress((void**)&py,   g_y);
    cudaGetSymbolAddress((void**)&ph,   g_h);
    cudaGetSymbolAddress((void**)&pwqkv,  g_wqkv);
    cudaGetSymbolAddress((void**)&pwfc,   g_wfc);
    cudaGetSymbolAddress((void**)&pw1,    g_w1);
    cudaGetSymbolAddress((void**)&pw2,    g_w2);
    cudaGetSymbolAddress((void**)&pwfc2t, g_wfc2t);

    static int smem_set = 0;
    if (!smem_set) {
        cudaFuncSetAttribute(attn_front,
                             cudaFuncAttributeMaxDynamicSharedMemorySize, AF_SMEM);
        smem_set = 1;
    }

    const int NE = TOK * EMB;

    prep_wT<<<CDIV(EMB*EMB3, 256), 256>>>(qkv_w, pwqkv, EMB, EMB3);
    prep_wT<<<CDIV(EMB*HIDDEN, 256), 256>>>(mlp_w1, pw1, EMB, HIDDEN);
    prep_wT<<<CDIV(HIDDEN*EMB, 256), 256>>>(mlp_w2, pw2, HIDDEN, EMB);
    prep_fcT<<<CDIV(256*SPAD, 256), 256>>>(fc_w, pwfc);
    prep_fc2T<<<CDIV(256*KWPAD, 256), 256>>>(fc2_w, pwfc2t);

    init_copy<<<CDIV(NE, 256), 256>>>(x, px1, px2, NE);

    for (int l = 0; l < NLAYERS; ++l) {
        // y1 = x1 + attention(LN_f(x2))
        ln_row768<<<TOK, 256>>>(px2, f_ln_g + l * EMB, f_ln_b + l * EMB, pxn);
        gemm_f16<4><<<dim3(EMB3/128, CDIV(TOK,128)), 256>>>(
            pxn, pwqkv, nullptr, nullptr, pqkv, nullptr, EMB3, TOK, EMB3, EMB);
        attn_front<<<dim3(2, BH), 256, AF_SMEM>>>(
            pqkv, pwfc, fc_b, attn_ln_g, attn_ln_b, pA);
        pv_f16<<<dim3(2, BH), 256>>>(pA, pqkv, py);
        out_f16<<<dim3(2, BH), 256>>>(pwfc2t, py, fc2_b, px1);
        // y2 = x2 + mlp(LN_g(y1))
        ln_row768<<<TOK, 256>>>(px1, gl_ln_g + l * EMB, gl_ln_b + l * EMB, pxn);
        gemm_f16<2><<<dim3(HIDDEN/128, CDIV(TOK,128)), 256>>>(
            pxn, pw1, mlp_b1, nullptr, ph, nullptr, HIDDEN, TOK, HIDDEN, EMB);
        gemm_f16<3><<<dim3(EMB/128, CDIV(TOK,128)), 256>>>(
            ph, pw2, mlp_b2, px2, nullptr, px2, EMB, TOK, EMB, HIDDEN);
    }

    finalize_k<<<CDIV(NE, 256), 256>>>(px1, px2, (float*)d_out, NE);
}

// round 7
// speedup vs baseline: 1.4997x; 1.4997x over previous
#include <cuda_runtime.h>
#include <cuda_fp16.h>
#include <math.h>
#include <stdint.h>

#define BATCH   32
#define SEQ     197
#define EMB     768
#define EMB3    2304
#define HEADS   12
#define HD      64
#define KW      197
#define NLAYERS 12
#define HIDDEN  3072
#define TOK     (BATCH*SEQ)       // 6304
#define BH      (BATCH*HEADS)     // 384
#define ROWSA   (BH*SEQ)          // 75648
#define SPAD    224               // padded stride for S and A rows (halfs)
#define KWPAD   208               // padded K for out kernel

#define CDIV(a,b) (((a)+(b)-1)/(b))

// ---------------- scratch ----------------
static __device__ float  g_x1 [TOK*EMB];
static __device__ float  g_x2 [TOK*EMB];
static __device__ __half g_xn [TOK*EMB];
static __device__ __half g_qkv[TOK*EMB3];
static __device__ __half g_S  [(size_t)BH*SEQ*SPAD];
static __device__ __half g_A  [(size_t)BH*SEQ*SPAD];
static __device__ __half g_y  [BH*KW*HD];
static __device__ __half g_h  [TOK*HIDDEN];
// half weights, pre-transposed to [N][K]
static __device__ __half g_wqkv [EMB3*EMB];
static __device__ __half g_wfc  [256*SPAD];
static __device__ __half g_w1   [HIDDEN*EMB];
static __device__ __half g_w2   [EMB*HIDDEN];
static __device__ __half g_wfc2t[256*KWPAD];

// ---------------- helpers ----------------
__device__ __forceinline__ void cpasync16(uint32_t dst, const void* src, int srcbytes) {
    asm volatile("cp.async.cg.shared.global [%0], [%1], 16, %2;\n"
                 :: "r"(dst), "l"(src), "r"(srcbytes));
}
__device__ __forceinline__ void cp_commit() { asm volatile("cp.async.commit_group;\n"); }
__device__ __forceinline__ void cp_wait0() { asm volatile("cp.async.wait_group 0;\n"); }
__device__ __forceinline__ void cp_wait1() { asm volatile("cp.async.wait_group 1;\n"); }

#define MMA_F16(acc, afr, bfr)                                               \
    asm volatile(                                                            \
        "mma.sync.aligned.m16n8k16.row.col.f32.f16.f16.f32 "                 \
        "{%0,%1,%2,%3}, {%4,%5,%6,%7}, {%8,%9}, {%0,%1,%2,%3};\n"            \
        : "+f"((acc)[0]), "+f"((acc)[1]), "+f"((acc)[2]), "+f"((acc)[3])     \
        : "r"((afr)[0]), "r"((afr)[1]), "r"((afr)[2]), "r"((afr)[3]),        \
          "r"((bfr)[0]), "r"((bfr)[1]))

#define LDSM_X4(r0, r1, r2, r3, addr)                                        \
    asm volatile("ldmatrix.sync.aligned.m8n8.x4.shared.b16 "                 \
                 "{%0,%1,%2,%3}, [%4];"                                      \
                 : "=r"(r0), "=r"(r1), "=r"(r2), "=r"(r3) : "r"(addr))

#define LDSM_X4_T(r0, r1, r2, r3, addr)                                      \
    asm volatile("ldmatrix.sync.aligned.m8n8.x4.trans.shared.b16 "           \
                 "{%0,%1,%2,%3}, [%4];"                                      \
                 : "=r"(r0), "=r"(r1), "=r"(r2), "=r"(r3) : "r"(addr))

// ---------------- elementwise ----------------
__global__ void init_copy(const float* __restrict__ x, float* __restrict__ x1,
                          float* __restrict__ x2, int n) {
    int i = blockIdx.x * blockDim.x + threadIdx.x;
    if (i < n) { float v = x[i]; x1[i] = v; x2[i] = v; }
}

__global__ void finalize_k(const float* __restrict__ x1, const float* __restrict__ x2,
                           float* __restrict__ out, int n) {
    int i = blockIdx.x * blockDim.x + threadIdx.x;
    if (i < n) out[i] = 0.5f * (x1[i] + x2[i]);
}

// transpose [K][N] float -> [N][K] half
__global__ void prep_wT(const float* __restrict__ s, __half* __restrict__ d,
                        int K, int N) {
    int i = blockIdx.x * blockDim.x + threadIdx.x;
    if (i < N * K) {
        int n = i / K, k = i % K;
        d[i] = __float2half_rn(s[(size_t)k * N + n]);
    }
}

// fc_w (SEQ,KW) -> Bt[256][SPAD]: Bt[n=kw][k=m]
__global__ void prep_fcT(const float* __restrict__ s, __half* __restrict__ d) {
    int i = blockIdx.x * blockDim.x + threadIdx.x;
    if (i < 256 * SPAD) {
        int n = i / SPAD, k = i % SPAD;
        d[i] = (n < KW && k < SEQ) ? __float2half_rn(s[k * KW + n]) : __float2half(0.f);
    }
}

// fc2_w (KW,SEQ) -> Wt[256][KWPAD]: Wt[n2][k=kw]
__global__ void prep_fc2T(const float* __restrict__ s, __half* __restrict__ d) {
    int i = blockIdx.x * blockDim.x + threadIdx.x;
    if (i < 256 * KWPAD) {
        int n2 = i / KWPAD, k = i % KWPAD;
        d[i] = (n2 < SEQ && k < KW) ? __float2half_rn(s[k * SEQ + n2]) : __float2half(0.f);
    }
}

__global__ void zero_pad_S(__half* __restrict__ S) {
    int i = blockIdx.x * blockDim.x + threadIdx.x;
    const int padw = SPAD - KW;
    if (i < ROWSA * padw) {
        int r = i / padw, c = KW + i % padw;
        S[(size_t)r * SPAD + c] = __float2half(0.f);
    }
}

// ---------------- layernorm rows of 768 -> half ----------------
__global__ void ln_row768(const float* __restrict__ x, const float* __restrict__ g,
                          const float* __restrict__ b, __half* __restrict__ out) {
    int row = blockIdx.x;
    const float* xr = x + (size_t)row * EMB;
    __half* orow = out + (size_t)row * EMB;
    int tid = threadIdx.x;  // 256
    float s = 0.f, ss = 0.f;
    for (int i = tid; i < EMB; i += 256) { float v = xr[i]; s += v; ss += v * v; }
    __shared__ float rs[8], rss[8];
    #pragma unroll
    for (int o = 16; o; o >>= 1) {
        s  += __shfl_xor_sync(0xffffffffu, s,  o);
        ss += __shfl_xor_sync(0xffffffffu, ss, o);
    }
    if ((tid & 31) == 0) { rs[tid >> 5] = s; rss[tid >> 5] = ss; }
    __syncthreads();
    if (tid < 32) {
        float a = (tid < 8) ? rs[tid]  : 0.f;
        float c = (tid < 8) ? rss[tid] : 0.f;
        #pragma unroll
        for (int o = 4; o; o >>= 1) {
            a += __shfl_xor_sync(0xffffffffu, a, o);
            c += __shfl_xor_sync(0xffffffffu, c, o);
        }
        if (tid == 0) { rs[0] = a; rss[0] = c; }
    }
    __syncthreads();
    float mu  = rs[0] * (1.0f / EMB);
    float var = rss[0] * (1.0f / EMB) - mu * mu;
    float inv = rsqrtf(var + 1e-5f);
    for (int i = tid; i < EMB; i += 256)
        orow[i] = __float2half_rn((xr[i] - mu) * inv * g[i] + b[i]);
}

// ================= fp16 GEMM: C = A[M,K] @ Bt[N,K]^T ======================
// 128x128x32 tiles, 3-stage cp.async pipeline, ldmatrix fragments.
// EPI: 1 +bias->half | 2 +bias,gelu->half | 3 +bias,+res->float | 4 ->half
#define GST 40           // smem tile stride in halfs
#define GSTG (128*GST)   // stage size in halfs (5120)

template <int EPI>
__global__ void __launch_bounds__(256) gemm_f16(
    const __half* __restrict__ A, const __half* __restrict__ B,
    const float* __restrict__ bias, const float* __restrict__ res,
    __half* __restrict__ Ch, float* __restrict__ Cf,
    int ldc, int M, int N, int K)
{
    __shared__ __half As[3 * GSTG];
    __shared__ __half Bs[3 * GSTG];
    const int tid  = threadIdx.x;
    const int warp = tid >> 5, lane = tid & 31;
    const int wm = warp >> 2, wn = warp & 3;
    const int g = lane >> 2, t = lane & 3;
    const int m0 = blockIdx.y * 128, n0 = blockIdx.x * 128;

    const uint32_t as_u = (uint32_t)__cvta_generic_to_shared(As);
    const uint32_t bs_u = (uint32_t)__cvta_generic_to_shared(Bs);

    const int r0i = tid >> 2, seg = (tid & 3) * 8;
    const int r1i = (tid + 256) >> 2;

    // ldmatrix lane->(row,col) offsets
    const int lrowA = (lane & 7) + ((lane >> 3) & 1) * 8;   // A: +8 rows on bit3
    const int lcolA = ((lane >> 4) & 1) * 8;                // A: +8 cols on bit4
    const int lrowB = (lane & 7) + ((lane >> 4) & 1) * 8;   // B: +8 rows on bit4
    const int lcolB = ((lane >> 3) & 1) * 8;                // B: +8 cols on bit3

    float acc[4][4][4];
    #pragma unroll
    for (int i = 0; i < 4; i++)
        #pragma unroll
        for (int j = 0; j < 4; j++)
            #pragma unroll
            for (int r = 0; r < 4; r++) acc[i][j][r] = 0.f;

    const int nch = K / 32;

    // prefetch chunks 0 and 1 into stages 0 and 1
    #pragma unroll
    for (int p = 0; p < 2; p++) {
        const int k0 = p * 32;
        const int so = p * GSTG;
        cpasync16(as_u + (uint32_t)(so + r0i * GST + seg) * 2,
                  A + (size_t)(m0 + r0i) * K + k0 + seg, (m0 + r0i < M) ? 16 : 0);
        cpasync16(as_u + (uint32_t)(so + r1i * GST + seg) * 2,
                  A + (size_t)(m0 + r1i) * K + k0 + seg, (m0 + r1i < M) ? 16 : 0);
        cpasync16(bs_u + (uint32_t)(so + r0i * GST + seg) * 2,
                  B + (size_t)(n0 + r0i) * K + k0 + seg, 16);
        cpasync16(bs_u + (uint32_t)(so + r1i * GST + seg) * 2,
                  B + (size_t)(n0 + r1i) * K + k0 + seg, 16);
        cp_commit();
    }

    int st_c = 0;       // stage holding chunk c
    int st_p = 2;       // stage to prefetch chunk c+2 into
    for (int c = 0; c < nch; ++c) {
        if (c + 1 < nch) cp_wait1(); else cp_wait0();
        __syncthreads();

        if (c + 2 < nch) {
            const int k0 = (c + 2) * 32;
            const int so = st_p * GSTG;
            cpasync16(as_u + (uint32_t)(so + r0i * GST + seg) * 2,
                      A + (size_t)(m0 + r0i) * K + k0 + seg, (m0 + r0i < M) ? 16 : 0);
            cpasync16(as_u + (uint32_t)(so + r1i * GST + seg) * 2,
                      A + (size_t)(m0 + r1i) * K + k0 + seg, (m0 + r1i < M) ? 16 : 0);
            cpasync16(bs_u + (uint32_t)(so + r0i * GST + seg) * 2,
                      B + (size_t)(n0 + r0i) * K + k0 + seg, 16);
            cpasync16(bs_u + (uint32_t)(so + r1i * GST + seg) * 2,
                      B + (size_t)(n0 + r1i) * K + k0 + seg, 16);
            cp_commit();
        }

        const uint32_t a_base = as_u + (uint32_t)(st_c * GSTG) * 2;
        const uint32_t b_base = bs_u + (uint32_t)(st_c * GSTG) * 2;

        #pragma unroll
        for (int kk = 0; kk < 2; ++kk) {
            const int kb = kk * 16;   // half offset of k16-step
            uint32_t afr[4][4], bfr[4][2];
            #pragma unroll
            for (int mi = 0; mi < 4; mi++) {
                int m = wm * 64 + mi * 16;
                uint32_t addr = a_base +
                    (uint32_t)((m + lrowA) * GST + kb + lcolA) * 2;
                LDSM_X4(afr[mi][0], afr[mi][1], afr[mi][2], afr[mi][3], addr);
            }
            #pragma unroll
            for (int njp = 0; njp < 2; njp++) {
                int n = wn * 32 + njp * 16;
                uint32_t addr = b_base +
                    (uint32_t)((n + lrowB) * GST + kb + lcolB) * 2;
                LDSM_X4(bfr[njp * 2][0], bfr[njp * 2][1],
                        bfr[njp * 2 + 1][0], bfr[njp * 2 + 1][1], addr);
            }
            #pragma unroll
            for (int mi = 0; mi < 4; mi++)
                #pragma unroll
                for (int nj = 0; nj < 4; nj++)
                    MMA_F16(acc[mi][nj], afr[mi], bfr[nj]);
        }
        st_c = (st_c == 2) ? 0 : st_c + 1;
        st_p = (st_p == 2) ? 0 : st_p + 1;
    }

    #pragma unroll
    for (int mi = 0; mi < 4; mi++) {
        int r0 = m0 + wm * 64 + mi * 16 + g;
        #pragma unroll
        for (int nj = 0; nj < 4; nj++) {
            int cb = n0 + wn * 32 + nj * 8 + 2 * t;
            #pragma unroll
            for (int half_ = 0; half_ < 2; half_++) {
                int gm = r0 + half_ * 8;
                if (gm >= M) continue;
                #pragma unroll
                for (int q = 0; q < 2; q++) {
                    int gn = cb + q;
                    if (gn >= N) continue;
                    float v = acc[mi][nj][half_ * 2 + q];
                    if (EPI == 1 || EPI == 2 || EPI == 3) v += bias[gn];
                    if (EPI == 2)
                        v = 0.5f * v * (1.0f + erff(v * 0.70710678118654752f));
                    if (EPI == 3)
                        Cf[(size_t)gm * ldc + gn] = v + res[(size_t)gm * ldc + gn];
                    else
                        Ch[(size_t)gm * ldc + gn] = __float2half_rn(v);
                }
            }
        }
    }
}

// ---------------- QK^T fp16 mma per (b,h): 128x128, K=64 -------------------
__global__ void __launch_bounds__(256) qk_f16(const __half* __restrict__ qkv,
                                              __half* __restrict__ S)
{
    __shared__ __half Qs[128 * 72];
    __shared__ __half Ks[128 * 72];
    const int z = blockIdx.z, b = z / HEADS, h = z % HEADS;
    const __half* qb = qkv + (size_t)b * SEQ * EMB3 + h * HD;
    const __half* kb = qb + EMB;
    const int m0 = blockIdx.y * 128, n0 = blockIdx.x * 128;
    const int tid = threadIdx.x;
    const int warp = tid >> 5, lane = tid & 31;
    const int wm = warp >> 2, wn = warp & 3;
    const int g = lane >> 2, t = lane & 3;
    const uint32_t qs_u = (uint32_t)__cvta_generic_to_shared(Qs);
    const uint32_t ks_u = (uint32_t)__cvta_generic_to_shared(Ks);

    #pragma unroll
    for (int i = 0; i < 4; i++) {
        int s = tid + i * 256;
        int r = s >> 3, sg = (s & 7) * 8;
        cpasync16(qs_u + (size_t)(r * 72 + sg) * 2,
                  qb + (size_t)(m0 + r) * EMB3 + sg, (m0 + r < SEQ) ? 16 : 0);
        cpasync16(ks_u + (size_t)(r * 72 + sg) * 2,
                  kb + (size_t)(n0 + r) * EMB3 + sg, (n0 + r < SEQ) ? 16 : 0);
    }
    cp_commit(); cp_wait0();
    __syncthreads();

    float acc[4][4][4];
    #pragma unroll
    for (int i = 0; i < 4; i++)
        #pragma unroll
        for (int j = 0; j < 4; j++)
            #pragma unroll
            for (int r = 0; r < 4; r++) acc[i][j][r] = 0.f;

    const uint32_t* qs32 = (const uint32_t*)Qs;
    const uint32_t* ks32 = (const uint32_t*)Ks;
    #pragma unroll
    for (int kk = 0; kk < 4; ++kk) {
        const int kb2 = kk * 8;
        uint32_t afr[4][4], bfr[4][2];
        #pragma unroll
        for (int mi = 0; mi < 4; mi++) {
            int m = wm * 64 + mi * 16 + g;
            afr[mi][0] = qs32[(m    ) * 36 + kb2 + t];
            afr[mi][1] = qs32[(m + 8) * 36 + kb2 + t];
            afr[mi][2] = qs32[(m    ) * 36 + kb2 + t + 4];
            afr[mi][3] = qs32[(m + 8) * 36 + kb2 + t + 4];
        }
        #pragma unroll
        for (int nj = 0; nj < 4; nj++) {
            int n = wn * 32 + nj * 8 + g;
            bfr[nj][0] = ks32[n * 36 + kb2 + t];
            bfr[nj][1] = ks32[n * 36 + kb2 + t + 4];
        }
        #pragma unroll
        for (int mi = 0; mi < 4; mi++)
            #pragma unroll
            for (int nj = 0; nj < 4; nj++)
                MMA_F16(acc[mi][nj], afr[mi], bfr[nj]);
    }

    __half* Sz = S + (size_t)z * SEQ * SPAD;
    #pragma unroll
    for (int mi = 0; mi < 4; mi++) {
        int r0 = m0 + wm * 64 + mi * 16 + g;
        #pragma unroll
        for (int nj = 0; nj < 4; nj++) {
            int cb = n0 + wn * 32 + nj * 8 + 2 * t;
            #pragma unroll
            for (int half_ = 0; half_ < 2; half_++) {
                int gm = r0 + half_ * 8;
                if (gm >= SEQ) continue;
                #pragma unroll
                for (int q = 0; q < 2; q++) {
                    int gn = cb + q;
                    if (gn >= SEQ) continue;
                    Sz[(size_t)gm * SPAD + gn] =
                        __float2half_rn(acc[mi][nj][half_ * 2 + q] * 0.125f);
                }
            }
        }
    }
}

// ---------------- fused LN(KW) + softmax(KW), warp per row (half) ----------
__global__ void ln_softmax(__half* __restrict__ A, const float* __restrict__ g,
                           const float* __restrict__ bb)
{
    int warp = (blockIdx.x * blockDim.x + threadIdx.x) >> 5;
    int lane = threadIdx.x & 31;
    if (warp >= ROWSA) return;
    __half* row = A + (size_t)warp * SPAD;
    float v[7];
    float s = 0.f, ss = 0.f;
    #pragma unroll
    for (int i = 0; i < 7; i++) {
        int idx = lane + i * 32;
        v[i] = (idx < KW) ? __half2float(row[idx]) : 0.f;
        s += v[i]; ss += v[i] * v[i];
    }
    #pragma unroll
    for (int o = 16; o; o >>= 1) {
        s  += __shfl_xor_sync(0xffffffffu, s,  o);
        ss += __shfl_xor_sync(0xffffffffu, ss, o);
    }
    float mu  = s * (1.0f / KW);
    float var = ss * (1.0f / KW) - mu * mu;
    float inv = rsqrtf(var + 1e-5f);
    float mx = -1e30f;
    #pragma unroll
    for (int i = 0; i < 7; i++) {
        int idx = lane + i * 32;
        if (idx < KW) {
            float zv = (v[i] - mu) * inv * g[idx] + bb[idx];
            v[i] = zv;
            mx = fmaxf(mx, zv);
        } else v[i] = -1e30f;
    }
    #pragma unroll
    for (int o = 16; o; o >>= 1) mx = fmaxf(mx, __shfl_xor_sync(0xffffffffu, mx, o));
    float se = 0.f;
    #pragma unroll
    for (int i = 0; i < 7; i++) {
        int idx = lane + i * 32;
        float e = (idx < KW) ? __expf(v[i] - mx) : 0.f;
        v[i] = e; se += e;
    }
    #pragma unroll
    for (int o = 16; o; o >>= 1) se += __shfl_xor_sync(0xffffffffu, se, o);
    float r = 1.0f / se;
    #pragma unroll
    for (int i = 0; i < 7; i++) {
        int idx = lane + i * 32;
        if (idx < KW) row[idx] = __float2half_rn(v[i] * r);
    }
}

// ---------------- P^T V fp16: y[z,kw,d] = sum_n P[n,kw] V[n,d] -------------
__global__ void __launch_bounds__(256) pv_f16(const __half* __restrict__ A,
                                              const __half* __restrict__ qkv,
                                              __half* __restrict__ y)
{
    __shared__ __half Ps[16 * 136];
    __shared__ __half Vs[16 * 72];
    const int z = blockIdx.y, b = z / HEADS, h = z % HEADS;
    const __half* Ab = A + (size_t)z * SEQ * SPAD;
    const __half* Vb = qkv + (size_t)b * SEQ * EMB3 + h * HD + 2 * EMB;
    const int m0 = blockIdx.x * 128;
    const int tid = threadIdx.x;
    const int warp = tid >> 5, lane = tid & 31;
    const int wm = warp >> 1, wn = warp & 1;
    const int g = lane >> 2, t = lane & 3;
    const uint32_t ps_u = (uint32_t)__cvta_generic_to_shared(Ps);
    const uint32_t vs_u = (uint32_t)__cvta_generic_to_shared(Vs);

    const int arow = (lane & 7) + ((lane >> 4) << 3);
    const int acol8 = ((lane >> 3) & 1) << 3;
    const int brow = (lane & 7) + (((lane >> 3) & 1) << 3);
    const int bcol8 = (lane >> 4) << 3;

    float acc[2][4][4];
    #pragma unroll
    for (int i = 0; i < 2; i++)
        #pragma unroll
        for (int j = 0; j < 4; j++)
            #pragma unroll
            for (int r = 0; r < 4; r++) acc[i][j][r] = 0.f;

    for (int c = 0; c < KWPAD / 16; ++c) {
        const int k0 = c * 16;
        {
            int r = tid >> 4, sg = (tid & 15) * 8;
            cpasync16(ps_u + (size_t)(r * 136 + sg) * 2,
                      Ab + (size_t)(k0 + r) * SPAD + m0 + sg,
                      (k0 + r < SEQ && m0 + sg < SPAD) ? 16 : 0);
        }
        if (tid < 128) {
            int r = tid >> 3, sg = (tid & 7) * 8;
            cpasync16(vs_u + (size_t)(r * 72 + sg) * 2,
                      Vb + (size_t)(k0 + r) * EMB3 + sg, (k0 + r < SEQ) ? 16 : 0);
        }
        cp_commit(); cp_wait0();
        __syncthreads();

        uint32_t afr[2][4], bfr[4][2];
        #pragma unroll
        for (int mi = 0; mi < 2; mi++) {
            uint32_t addr = ps_u + (size_t)(arow * 136 + wm * 32 + mi * 16 + acol8) * 2;
            LDSM_X4_T(afr[mi][0], afr[mi][1], afr[mi][2], afr[mi][3], addr);
        }
        #pragma unroll
        for (int njp = 0; njp < 2; njp++) {
            uint32_t addr = vs_u + (size_t)(brow * 72 + wn * 32 + njp * 16 + bcol8) * 2;
            LDSM_X4_T(bfr[njp * 2][0], bfr[njp * 2][1],
                      bfr[njp * 2 + 1][0], bfr[njp * 2 + 1][1], addr);
        }
        #pragma unroll
        for (int mi = 0; mi < 2; mi++)
            #pragma unroll
            for (int nj = 0; nj < 4; nj++)
                MMA_F16(acc[mi][nj], afr[mi], bfr[nj]);
        __syncthreads();
    }

    __half* yz = y + (size_t)z * KW * HD;
    #pragma unroll
    for (int mi = 0; mi < 2; mi++) {
        int r0 = m0 + wm * 32 + mi * 16 + g;
        #pragma unroll
        for (int nj = 0; nj < 4; nj++) {
            int cb = wn * 32 + nj * 8 + 2 * t;
            #pragma unroll
            for (int half_ = 0; half_ < 2; half_++) {
                int gm = r0 + half_ * 8;
                if (gm >= KW) continue;
                #pragma unroll
                for (int q = 0; q < 2; q++)
                    yz[(size_t)gm * HD + cb + q] =
                        __float2half_rn(acc[mi][nj][half_ * 2 + q]);
            }
        }
    }
}

// --------- fc2: x1[b,n2,h,d] += sum_k Wt[n2,k] y[z,k,d] + fc2_b[n2] --------
__global__ void __launch_bounds__(256) out_f16(const __half* __restrict__ Wt,
                                               const __half* __restrict__ y,
                                               const float* __restrict__ bias,
                                               float* __restrict__ x1)
{
    __shared__ __half As[128 * 24];
    __shared__ __half Ys[16 * 72];
    const int z = blockIdx.y, b = z / HEADS, h = z % HEADS;
    const __half* yb = y + (size_t)z * KW * HD;
    const int m0 = blockIdx.x * 128;
    const int tid = threadIdx.x;
    const int warp = tid >> 5, lane = tid & 31;
    const int wm = warp >> 1, wn = warp & 1;
    const int g = lane >> 2, t = lane & 3;
    const uint32_t as_u = (uint32_t)__cvta_generic_to_shared(As);
    const uint32_t ys_u = (uint32_t)__cvta_generic_to_shared(Ys);

    const int brow = (lane & 7) + (((lane >> 3) & 1) << 3);
    const int bcol8 = (lane >> 4) << 3;

    float acc[2][4][4];
    #pragma unroll
    for (int i = 0; i < 2; i++)
        #pragma unroll
        for (int j = 0; j < 4; j++)
            #pragma unroll
            for (int r = 0; r < 4; r++) acc[i][j][r] = 0.f;

    for (int c = 0; c < KWPAD / 16; ++c) {
        const int k0 = c * 16;
        {
            int r = tid >> 1, sg = (tid & 1) * 8;
            cpasync16(as_u + (size_t)(r * 24 + sg) * 2,
                      Wt + (size_t)(m0 + r) * KWPAD + k0 + sg, 16);
        }
        if (tid < 128) {
            int r = tid >> 3, sg = (tid & 7) * 8;
            cpasync16(ys_u + (size_t)(r * 72 + sg) * 2,
                      yb + (size_t)(k0 + r) * HD + sg, (k0 + r < KW) ? 16 : 0);
        }
        cp_commit(); cp_wait0();
        __syncthreads();

        const uint32_t* as32 = (const uint32_t*)As;
        uint32_t afr[2][4], bfr[4][2];
        #pragma unroll
        for (int mi = 0; mi < 2; mi++) {
            int m = wm * 32 + mi * 16 + g;
            afr[mi][0] = as32[(m    ) * 12 + t];
            afr[mi][1] = as32[(m + 8) * 12 + t];
            afr[mi][2] = as32[(m    ) * 12 + t + 4];
            afr[mi][3] = as32[(m + 8) * 12 + t + 4];
        }
        #pragma unroll
        for (int njp = 0; njp < 2; njp++) {
            uint32_t addr = ys_u + (size_t)(brow * 72 + wn * 32 + njp * 16 + bcol8) * 2;
            LDSM_X4_T(bfr[njp * 2][0], bfr[njp * 2][1],
                      bfr[njp * 2 + 1][0], bfr[njp * 2 + 1][1], addr);
        }
        #pragma unroll
        for (int mi = 0; mi < 2; mi++)
            #pragma unroll
            for (int nj = 0; nj < 4; nj++)
                MMA_F16(acc[mi][nj], afr[mi], bfr[nj]);
        __syncthreads();
    }

    #pragma unroll
    for (int mi = 0; mi < 2; mi++) {
        int r0 = m0 + wm * 32 + mi * 16 + g;
        #pragma unroll
        for (int nj = 0; nj < 4; nj++) {
            int cb = wn * 32 + nj * 8 + 2 * t;
            #pragma unroll
            for (int half_ = 0; half_ < 2; half_++) {
                int gm = r0 + half_ * 8;
                if (gm >= SEQ) continue;
                float bv = bias[gm];
                #pragma unroll
                for (int q = 0; q < 2; q++) {
                    size_t idx = ((size_t)(b * SEQ + gm)) * EMB + h * HD + cb + q;
                    x1[idx] += acc[mi][nj][half_ * 2 + q] + bv;
                }
            }
        }
    }
}

// ---------------- launch ----------------
extern "C" void kernel_launch(void* const* d_in, const int* in_sizes, int n_in,
                              void* d_out, int out_size) {
    (void)in_sizes; (void)n_in; (void)out_size;
    const float* x         = (const float*)d_in[0];
    const float* qkv_w     = (const float*)d_in[1];
    const float* fc_w      = (const float*)d_in[2];
    const float* fc_b      = (const float*)d_in[3];
    const float* attn_ln_g = (const float*)d_in[4];
    const float* attn_ln_b = (const float*)d_in[5];
    const float* fc2_w     = (const float*)d_in[6];
    const float* fc2_b     = (const float*)d_in[7];
    const float* mlp_w1    = (const float*)d_in[8];
    const float* mlp_b1    = (const float*)d_in[9];
    const float* mlp_w2    = (const float*)d_in[10];
    const float* mlp_b2    = (const float*)d_in[11];
    const float* f_ln_g    = (const float*)d_in[12];
    const float* f_ln_b    = (const float*)d_in[13];
    const float* gl_ln_g   = (const float*)d_in[14];
    const float* gl_ln_b   = (const float*)d_in[15];

    float *px1, *px2;
    __half *pxn, *pqkv, *pS, *pA, *py, *ph;
    __half *pwqkv, *pwfc, *pw1, *pw2, *pwfc2t;
    cudaGetSymbolAddress((void**)&px1,  g_x1);
    cudaGetSymbolAddress((void**)&px2,  g_x2);
    cudaGetSymbolAddress((void**)&pxn,  g_xn);
    cudaGetSymbolAddress((void**)&pqkv, g_qkv);
    cudaGetSymbolAddress((void**)&pS,   g_S);
    cudaGetSymbolAddress((void**)&pA,   g_A);
    cudaGetSymbolAddress((void**)&py,   g_y);
    cudaGetSymbolAddress((void**)&ph,   g_h);
    cudaGetSymbolAddress((void**)&pwqkv,  g_wqkv);
    cudaGetSymbolAddress((void**)&pwfc,   g_wfc);
    cudaGetSymbolAddress((void**)&pw1,    g_w1);
    cudaGetSymbolAddress((void**)&pw2,    g_w2);
    cudaGetSymbolAddress((void**)&pwfc2t, g_wfc2t);

    const int NE = TOK * EMB;

    prep_wT<<<CDIV(EMB*EMB3, 256), 256>>>(qkv_w, pwqkv, EMB, EMB3);
    prep_wT<<<CDIV(EMB*HIDDEN, 256), 256>>>(mlp_w1, pw1, EMB, HIDDEN);
    prep_wT<<<CDIV(HIDDEN*EMB, 256), 256>>>(mlp_w2, pw2, HIDDEN, EMB);
    prep_fcT<<<CDIV(256*SPAD, 256), 256>>>(fc_w, pwfc);
    prep_fc2T<<<CDIV(256*KWPAD, 256), 256>>>(fc2_w, pwfc2t);
    zero_pad_S<<<CDIV(ROWSA*(SPAD-KW), 256), 256>>>(pS);

    init_copy<<<CDIV(NE, 256), 256>>>(x, px1, px2, NE);

    for (int l = 0; l < NLAYERS; ++l) {
        // y1 = x1 + attention(LN_f(x2))
        ln_row768<<<TOK, 256>>>(px2, f_ln_g + l * EMB, f_ln_b + l * EMB, pxn);
        gemm_f16<4><<<dim3(EMB3/128, CDIV(TOK,128)), 256>>>(
            pxn, pwqkv, nullptr, nullptr, pqkv, nullptr, EMB3, TOK, EMB3, EMB);
        qk_f16<<<dim3(2, 2, BH), 256>>>(pqkv, pS);
        gemm_f16<1><<<dim3(CDIV(KW,128), CDIV(ROWSA,128)), 256>>>(
            pS, pwfc, fc_b, nullptr, pA, nullptr, SPAD, ROWSA, KW, SPAD);
        ln_softmax<<<ROWSA / 8, 256>>>(pA, attn_ln_g, attn_ln_b);
        pv_f16<<<dim3(2, BH), 256>>>(pA, pqkv, py);
        out_f16<<<dim3(2, BH), 256>>>(pwfc2t, py, fc2_b, px1);
        // y2 = x2 + mlp(LN_g(y1))
        ln_row768<<<TOK, 256>>>(px1, gl_ln_g + l * EMB, gl_ln_b + l * EMB, pxn);
        gemm_f16<2><<<dim3(HIDDEN/128, CDIV(TOK,128)), 256>>>(
            pxn, pw1, mlp_b1, nullptr, ph, nullptr, HIDDEN, TOK, HIDDEN, EMB);
        gemm_f16<3><<<dim3(EMB/128, CDIV(TOK,128)), 256>>>(
            ph, pw2, mlp_b2, px2, nullptr, px2, EMB, TOK, EMB, HIDDEN);
    }

    finalize_k<<<CDIV(NE, 256), 256>>>(px1, px2, (float*)d_out, NE);
}